// round 4
// baseline (speedup 1.0000x reference)
#include <cuda_runtime.h>
#include <cstdint>

#define T_SEQ 1024
#define B_SZ  256

// ---------------- device scratch (allocation-free statics) ----------------
__device__ float g_X0[1024u * 256u * 64u];     // conv out [t][b][64]  (64 MB)
__device__ float g_XW[268435456u];             // xw [t*B+b][<=1024]   (1 GB)
__device__ float g_Y [67108864u];              // layer out [t*B+b][256] (256 MB)
__device__ float g_XWB3[256 * 256];            // layer3 bwd xw at t=T-1
__device__ float g_H3[256 * 128];              // final features
__device__ float g_F1[256 * 512];
__device__ float g_F2[256 * 256];
__device__ float g_F3[256 * 128];

// ---------------- activations ----------------
__device__ __forceinline__ float sigf(float x) {
    return __fdividef(1.0f, 1.0f + __expf(-x));
}
__device__ __forceinline__ float tanhf_(float x) {
    return __fdividef(2.0f, 1.0f + __expf(-2.0f * x)) - 1.0f;
}

// ---------------- conv1d (causal k=5, 1->64) + relu -> [t][b][64] ----------
__global__ void conv_kernel(const float* __restrict__ x, const float* __restrict__ w,
                            const float* __restrict__ bias, float* __restrict__ out)
{
    int tid = threadIdx.x;            // 256
    int c   = tid & 63;
    int ts  = tid >> 6;
    int t   = blockIdx.x * 4 + ts;
    int b   = blockIdx.y;
    float acc = bias[c];
#pragma unroll
    for (int k = 0; k < 5; k++) {
        int xi = t - 4 + k;
        float xv = (xi >= 0) ? x[(size_t)b * T_SEQ + xi] : 0.0f;
        acc = fmaf(xv, w[c * 5 + k], acc);
    }
    out[((size_t)t * B_SZ + b) * 64 + c] = fmaxf(acc, 0.0f);
}

// ---------------- fp32 GEMM: C[m][n] = sum_k A[m][k]*W[n][k] + bias[n] ------
// M%128==0, N%128==0, K%8==0.  128x128 tile, 256 threads, 8x8 micro-tile.
__global__ __launch_bounds__(256, 2)
void gemm_tn(const float* __restrict__ A, const float* __restrict__ W,
             const float* __restrict__ bias, float* __restrict__ C,
             int M, int N, int K)
{
    __shared__ float As[8][128];
    __shared__ float Bs[8][128];
    int tid = threadIdx.x;
    int m0 = blockIdx.x * 128;
    int n0 = blockIdx.y * 128;

    int lr = tid >> 1;
    int lc = (tid & 1) * 4;
    const float* Ap = A + (size_t)(m0 + lr) * K + lc;
    const float* Wp = W + (size_t)(n0 + lr) * K + lc;

    int tm = (tid >> 4) * 8;   // 0..120
    int tn = (tid & 15) * 8;   // 0..120

    float acc[8][8];
#pragma unroll
    for (int i = 0; i < 8; i++)
#pragma unroll
        for (int j = 0; j < 8; j++) acc[i][j] = 0.0f;

    for (int k0 = 0; k0 < K; k0 += 8) {
        float4 av = *(const float4*)(Ap + k0);
        float4 wv = *(const float4*)(Wp + k0);
        __syncthreads();
        As[lc + 0][lr] = av.x; As[lc + 1][lr] = av.y;
        As[lc + 2][lr] = av.z; As[lc + 3][lr] = av.w;
        Bs[lc + 0][lr] = wv.x; Bs[lc + 1][lr] = wv.y;
        Bs[lc + 2][lr] = wv.z; Bs[lc + 3][lr] = wv.w;
        __syncthreads();
#pragma unroll
        for (int kk = 0; kk < 8; kk++) {
            float4 a0 = *(const float4*)&As[kk][tm];
            float4 a1 = *(const float4*)&As[kk][tm + 4];
            float4 b0 = *(const float4*)&Bs[kk][tn];
            float4 b1 = *(const float4*)&Bs[kk][tn + 4];
            float av8[8] = {a0.x, a0.y, a0.z, a0.w, a1.x, a1.y, a1.z, a1.w};
            float bv8[8] = {b0.x, b0.y, b0.z, b0.w, b1.x, b1.y, b1.z, b1.w};
#pragma unroll
            for (int i = 0; i < 8; i++)
#pragma unroll
                for (int j = 0; j < 8; j++)
                    acc[i][j] = fmaf(av8[i], bv8[j], acc[i][j]);
        }
    }

    float bv[8];
#pragma unroll
    for (int j = 0; j < 8; j++) bv[j] = bias[n0 + tn + j];
#pragma unroll
    for (int i = 0; i < 8; i++) {
        size_t row = (size_t)(m0 + tm + i) * N + n0 + tn;
#pragma unroll
        for (int j = 0; j < 8; j += 4) {
            float4 v;
            v.x = acc[i][j + 0] + bv[j + 0];
            v.y = acc[i][j + 1] + bv[j + 1];
            v.z = acc[i][j + 2] + bv[j + 2];
            v.w = acc[i][j + 3] + bv[j + 3];
            *(float4*)&C[row + j] = v;
        }
    }
}

// ---------------- recurrent LSTM scan -------------------------------------
// Block = 4H threads (one per gate column). One CTA = NB batch rows, one dir.
// W_hh^T cached: k-rows [0,KS) in smem as Wt[k][g]; k-rows [KS,H) in registers.
// xw read streamed from global each step (coalesced). h double-buffered in smem.
template<int H, int NB, int KS, int NREG, int LDXW, bool LAST_ONLY>
__global__ __launch_bounds__(4 * H, 1)
void lstm_kernel(const float* __restrict__ xw,    // [T*B][LDXW], dir off = dir*4H
                 const float* __restrict__ w_hh,  // [dirs][4H][H]
                 float* __restrict__ y)           // [T*B][256] or [B][128]
{
    constexpr int G4 = 4 * H;
    const int g   = threadIdx.x;
    const int dir = blockIdx.y;
    const int b0  = blockIdx.x * NB;

    extern __shared__ float sm[];
    float* Wt    = sm;                      // [KS][G4]
    float* hbuf  = Wt + KS * G4;            // [H][NB]
    float* gates = hbuf + H * NB;           // [NB][G4]

    const float* Wrow = w_hh + (size_t)dir * G4 * H + (size_t)g * H;
    for (int k = 0; k < KS; k++) Wt[k * G4 + g] = Wrow[k];
    float wreg[NREG > 0 ? NREG : 1];
    if constexpr (NREG > 0) {
#pragma unroll
        for (int kk = 0; kk < NREG; kk++) wreg[kk] = Wrow[KS + kk];
    }
    for (int i = g; i < H * NB; i += G4) hbuf[i] = 0.0f;
    float creg = 0.0f;
    __syncthreads();

    const int tstep = (dir == 0) ? 1 : -1;
    int t = (dir == 0) ? 0 : (T_SEQ - 1);

    for (int s = 0; s < T_SEQ; s++, t += tstep) {
        const float* xr = xw + ((size_t)t * B_SZ + b0) * LDXW + dir * G4;
        float acc[NB];
#pragma unroll
        for (int nb = 0; nb < NB; nb++) acc[nb] = xr[(size_t)nb * LDXW + g];

        if constexpr (NB == 4) {
#pragma unroll 8
            for (int k = 0; k < KS; k++) {
                float w = Wt[k * G4 + g];
                float4 h4 = *(const float4*)(hbuf + k * 4);
                acc[0] = fmaf(w, h4.x, acc[0]);
                acc[1] = fmaf(w, h4.y, acc[1]);
                acc[2] = fmaf(w, h4.z, acc[2]);
                acc[3] = fmaf(w, h4.w, acc[3]);
            }
            if constexpr (NREG > 0) {
#pragma unroll
                for (int kk = 0; kk < NREG; kk++) {
                    float4 h4 = *(const float4*)(hbuf + (KS + kk) * 4);
                    acc[0] = fmaf(wreg[kk], h4.x, acc[0]);
                    acc[1] = fmaf(wreg[kk], h4.y, acc[1]);
                    acc[2] = fmaf(wreg[kk], h4.z, acc[2]);
                    acc[3] = fmaf(wreg[kk], h4.w, acc[3]);
                }
            }
        } else {
#pragma unroll 8
            for (int k = 0; k < KS; k++) {
                float w = Wt[k * G4 + g];
                float2 h2 = *(const float2*)(hbuf + k * 2);
                acc[0] = fmaf(w, h2.x, acc[0]);
                acc[1] = fmaf(w, h2.y, acc[1]);
            }
        }

#pragma unroll
        for (int nb = 0; nb < NB; nb++) gates[nb * G4 + g] = acc[nb];
        __syncthreads();

        // unit update: thread u < NB*H handles (nb, j)
        if (g < NB * H) {
            int nb = g / H, j = g % H;
            const float* gr = gates + nb * G4;
            float xi = gr[j];
            float xf = gr[H + j];
            float xg = gr[2 * H + j];
            float xo = gr[3 * H + j];
            float si = sigf(xi), sf = sigf(xf), so = sigf(xo);
            float tg = tanhf_(xg);
            creg = fmaf(sf, creg, si * tg);
            float h = so * tanhf_(creg);
            hbuf[j * NB + nb] = h;
            if constexpr (LAST_ONLY) {
                if (s == T_SEQ - 1) y[(size_t)(b0 + nb) * 128 + j] = h;
            } else {
                y[((size_t)t * B_SZ + b0 + nb) * 256 + dir * H + j] = h;
            }
        }
        __syncthreads();
    }
}

// ---------------- layer-3 backward: single step from zero state -----------
__global__ void lstm3_bwd_last(const float* __restrict__ xwb, float* __restrict__ h3)
{
    int b = blockIdx.x;
    int j = threadIdx.x;  // 0..63
    const float* gr = xwb + b * 256;
    float xi = gr[j], xf_unused = gr[64 + j], xg = gr[128 + j], xo = gr[192 + j];
    (void)xf_unused;  // sig(f)*c0 = 0
    float c = sigf(xi) * tanhf_(xg);
    float h = sigf(xo) * tanhf_(c);
    h3[b * 128 + 64 + j] = h;
}

// ---------------- small FC: out[b][o] = act(in[b] . w[o] + bias[o]) --------
__global__ void fc_kernel(const float* __restrict__ in, const float* __restrict__ w,
                          const float* __restrict__ bias, float* __restrict__ out,
                          int K, int O, int do_relu)
{
    int b = blockIdx.x;
    extern __shared__ float s_in[];
    for (int k = threadIdx.x; k < K; k += blockDim.x) s_in[k] = in[(size_t)b * K + k];
    __syncthreads();
    for (int o = threadIdx.x; o < O; o += blockDim.x) {
        float acc = bias[o];
        const float* wr = w + (size_t)o * K;
        for (int k = 0; k < K; k++) acc = fmaf(s_in[k], wr[k], acc);
        if (do_relu) acc = fmaxf(acc, 0.0f);
        out[(size_t)b * O + o] = acc;
    }
}

// ---------------- host orchestration --------------------------------------
extern "C" void kernel_launch(void* const* d_in, const int* in_sizes, int n_in,
                              void* d_out, int out_size)
{
    const float* x      = (const float*)d_in[0];
    const float* conv_w = (const float*)d_in[1];
    const float* conv_b = (const float*)d_in[2];
    const float* w_ih1  = (const float*)d_in[3];
    const float* w_hh1  = (const float*)d_in[4];
    const float* b1     = (const float*)d_in[5];
    const float* w_ih2  = (const float*)d_in[6];
    const float* w_hh2  = (const float*)d_in[7];
    const float* b2     = (const float*)d_in[8];
    const float* w_ih3  = (const float*)d_in[9];
    const float* w_hh3  = (const float*)d_in[10];
    const float* b3     = (const float*)d_in[11];
    const float* fc1_w  = (const float*)d_in[12];
    const float* fc1_b  = (const float*)d_in[13];
    const float* fc2_w  = (const float*)d_in[14];
    const float* fc2_b  = (const float*)d_in[15];
    const float* fc3_w  = (const float*)d_in[16];
    const float* fc3_b  = (const float*)d_in[17];
    const float* fc4_w  = (const float*)d_in[18];
    const float* fc4_b  = (const float*)d_in[19];
    float* out = (float*)d_out;

    float *pX0, *pXW, *pY, *pXWB3, *pH3, *pF1, *pF2, *pF3;
    cudaGetSymbolAddress((void**)&pX0,   g_X0);
    cudaGetSymbolAddress((void**)&pXW,   g_XW);
    cudaGetSymbolAddress((void**)&pY,    g_Y);
    cudaGetSymbolAddress((void**)&pXWB3, g_XWB3);
    cudaGetSymbolAddress((void**)&pH3,   g_H3);
    cudaGetSymbolAddress((void**)&pF1,   g_F1);
    cudaGetSymbolAddress((void**)&pF2,   g_F2);
    cudaGetSymbolAddress((void**)&pF3,   g_F3);

    const int M = T_SEQ * B_SZ;  // 262144

    // lstm128: KS=104 rows in smem, 24 in registers
    constexpr int SMEM128 = (104 * 512 + 128 * 4 + 4 * 512) * 4;  // 223232 B
    constexpr int SMEM64  = (64 * 256 + 64 * 2 + 2 * 256) * 4;    //  68096 B
    cudaFuncSetAttribute(lstm_kernel<128, 4, 104, 24, 1024, false>,
                         cudaFuncAttributeMaxDynamicSharedMemorySize, SMEM128);
    cudaFuncSetAttribute(lstm_kernel<64, 2, 64, 0, 256, true>,
                         cudaFuncAttributeMaxDynamicSharedMemorySize, SMEM64);

    // 1) conv -> X0 [t][b][64]
    conv_kernel<<<dim3(T_SEQ / 4, B_SZ), 256>>>(x, conv_w, conv_b, pX0);

    // 2) layer 1: XW = X0 @ w_ih1^T + b1   (N=1024 both dirs)
    gemm_tn<<<dim3(M / 128, 1024 / 128), 256>>>(pX0, w_ih1, b1, pXW, M, 1024, 64);
    lstm_kernel<128, 4, 104, 24, 1024, false>
        <<<dim3(B_SZ / 4, 2), 512, SMEM128>>>(pXW, w_hh1, pY);

    // 3) layer 2
    gemm_tn<<<dim3(M / 128, 1024 / 128), 256>>>(pY, w_ih2, b2, pXW, M, 1024, 256);
    lstm_kernel<128, 4, 104, 24, 1024, false>
        <<<dim3(B_SZ / 4, 2), 512, SMEM128>>>(pXW, w_hh2, pY);

    // 4) layer 3 forward: full scan, keep only last h
    gemm_tn<<<dim3(M / 128, 256 / 128), 256>>>(pY, w_ih3, b3, pXW, M, 256, 256);
    lstm_kernel<64, 2, 64, 0, 256, true>
        <<<dim3(B_SZ / 2, 1), 256, SMEM64>>>(pXW, w_hh3, pH3);

    // 5) layer 3 backward at t=T-1 only: one step from zero state
    gemm_tn<<<dim3(256 / 128, 256 / 128), 256>>>(
        pY + (size_t)(T_SEQ - 1) * B_SZ * 256,
        w_ih3 + 256 * 256, b3 + 256, pXWB3, 256, 256, 256);
    lstm3_bwd_last<<<B_SZ, 64>>>(pXWB3, pH3);

    // 6) FC head
    fc_kernel<<<B_SZ, 128, 128 * 4>>>(pH3, fc1_w, fc1_b, pF1, 128, 512, 1);
    fc_kernel<<<B_SZ, 128, 512 * 4>>>(pF1, fc2_w, fc2_b, pF2, 512, 256, 1);
    fc_kernel<<<B_SZ, 128, 256 * 4>>>(pF2, fc3_w, fc3_b, pF3, 256, 128, 1);
    fc_kernel<<<B_SZ, 64, 128 * 4>>>(pF3, fc4_w, fc4_b, out, 128, 2, 0);

    (void)in_sizes; (void)n_in; (void)out_size;
}

// round 6
// speedup vs baseline: 1.1629x; 1.1629x over previous
#include <cuda_runtime.h>
#include <cuda_bf16.h>
#include <cstdint>

#define T_SEQ 1024
#define B_SZ  256

// ---------------- device scratch (allocation-free statics) ----------------
__device__ float g_X0[1024u * 256u * 64u];          // conv out [t][b][64]
__device__ float g_XW[262144ull * 1024];            // xw fp32 [t*B+b][<=1024]
__device__ float g_Y [262144ull * 256];             // layer out [t*B+b][256]
__device__ __nv_bfloat16 g_Ap[262144ull * 768];     // split-bf16 A' [row][3K]
__device__ __nv_bfloat16 g_Wp[1024ull * 768];       // split-bf16 W' [row][3K]
__device__ float g_XWB3[256 * 256];
__device__ float g_H3[256 * 128];
__device__ float g_F1[256 * 512];
__device__ float g_F2[256 * 256];
__device__ float g_F3[256 * 128];

// ---------------- portable PTX helpers (sm_80+ features only) -------------
__device__ __forceinline__ uint32_t smem_to_u32(const void* p) {
    uint32_t a;
    asm("{ .reg .u64 t; cvta.to.shared.u64 t, %1; cvt.u32.u64 %0, t; }" : "=r"(a) : "l"(p));
    return a;
}
__device__ __forceinline__ void cp_async16(uint32_t dst, const void* src) {
    asm volatile("cp.async.cg.shared.global [%0], [%1], 16;" :: "r"(dst), "l"(src) : "memory");
}
__device__ __forceinline__ void cp_commit() {
    asm volatile("cp.async.commit_group;" ::: "memory");
}
template<int N>
__device__ __forceinline__ void cp_wait() {
    asm volatile("cp.async.wait_group %0;" :: "n"(N) : "memory");
}
#define LDSM_X4(r, addr) \
    asm volatile("ldmatrix.sync.aligned.m8n8.x4.shared.b16 {%0,%1,%2,%3}, [%4];" \
        : "=r"((r)[0]), "=r"((r)[1]), "=r"((r)[2]), "=r"((r)[3]) : "r"(addr))
#define MMA16816(d, a, b0, b1) \
    asm volatile("mma.sync.aligned.m16n8k16.row.col.f32.bf16.bf16.f32 " \
        "{%0,%1,%2,%3}, {%4,%5,%6,%7}, {%8,%9}, {%0,%1,%2,%3};" \
        : "+f"((d)[0]), "+f"((d)[1]), "+f"((d)[2]), "+f"((d)[3]) \
        : "r"((a)[0]), "r"((a)[1]), "r"((a)[2]), "r"((a)[3]), "r"(b0), "r"(b1))

// ---------------- activations ----------------
__device__ __forceinline__ float sigf(float x) {
    return __fdividef(1.0f, 1.0f + __expf(-x));
}
__device__ __forceinline__ float tanhf_(float x) {
    return __fdividef(2.0f, 1.0f + __expf(-2.0f * x)) - 1.0f;
}

// ---------------- conv1d (causal k=5, 1->64) + relu -> [t][b][64] ----------
__global__ void conv_kernel(const float* __restrict__ x, const float* __restrict__ w,
                            const float* __restrict__ bias, float* __restrict__ out)
{
    int tid = threadIdx.x;            // 256
    int c   = tid & 63;
    int ts  = tid >> 6;
    int t   = blockIdx.x * 4 + ts;
    int b   = blockIdx.y;
    float acc = bias[c];
#pragma unroll
    for (int k = 0; k < 5; k++) {
        int xi = t - 4 + k;
        float xv = (xi >= 0) ? x[(size_t)b * T_SEQ + xi] : 0.0f;
        acc = fmaf(xv, w[c * 5 + k], acc);
    }
    out[((size_t)t * B_SZ + b) * 64 + c] = fmaxf(acc, 0.0f);
}

// ---------------- split fp32 -> bf16 along K --------------------------------
// A pattern (wpat=0): [hi, hi, lo] ;  W pattern (wpat=1): [hi, lo, hi]
__global__ void split2_kernel(const float* __restrict__ src, __nv_bfloat16* __restrict__ dst,
                              int total2, int Khalf, int K, int wpat)
{
    int i = blockIdx.x * blockDim.x + threadIdx.x;
    if (i >= total2) return;
    int r = i / Khalf;
    int k = (i - r * Khalf) * 2;
    float2 v = *(const float2*)(src + (size_t)r * K + k);
    __nv_bfloat16 hx = __float2bfloat16(v.x);
    __nv_bfloat16 hy = __float2bfloat16(v.y);
    __nv_bfloat16 lx = __float2bfloat16(v.x - __bfloat162float(hx));
    __nv_bfloat16 ly = __float2bfloat16(v.y - __bfloat162float(hy));
    __nv_bfloat162 hi; hi.x = hx; hi.y = hy;
    __nv_bfloat162 lo; lo.x = lx; lo.y = ly;
    __nv_bfloat16* d = dst + (size_t)r * 3 * K + k;
    *(__nv_bfloat162*)(d)         = hi;
    *(__nv_bfloat162*)(d + K)     = wpat ? lo : hi;
    *(__nv_bfloat162*)(d + 2 * K) = wpat ? hi : lo;
}

// ---------------- HMMA GEMM: C[m][n] = sum_k A'[m][k] W'[n][k] + bias[n] ----
// Tile 128x128, BK=32 bf16, 4-stage cp.async pipeline, 8 warps (32m x 64n).
// smem tile rows padded to 40 bf16 (80 B): ldmatrix conflict-free (5r mod 8).
#define GSTAGES 4
#define LDT_B   80                 // bytes per smem tile row
#define TILE_B  (128 * LDT_B)      // 10240 B per operand tile
#define STAGE_B (2 * TILE_B)       // 20480 B per stage
#define GSMEM   (GSTAGES * STAGE_B)

__global__ __launch_bounds__(256)
void gemm_mma(const __nv_bfloat16* __restrict__ A, const __nv_bfloat16* __restrict__ W,
              const float* __restrict__ bias, float* __restrict__ C,
              int Kp, int ldc)
{
    extern __shared__ char sm[];
    const uint32_t sbase = smem_to_u32(sm);
    const int tid  = threadIdx.x;
    const int wid  = tid >> 5, lane = tid & 31;
    const int wm   = wid & 3;          // warp m index (32 rows each)
    const int wn   = wid >> 2;         // warp n index (64 cols each)
    const int n0   = blockIdx.x * 128;
    const int m0   = blockIdx.y * 128;
    const int NK   = Kp >> 5;          // k-blocks of 32
    const size_t rowBytes = (size_t)Kp * 2;

    const char* Ag = (const char*)(A + (size_t)m0 * Kp);
    const char* Wg = (const char*)(W + (size_t)n0 * Kp);

    // per-thread load slots: row = tid>>1, two 16B chunks
    const int lrow = tid >> 1;
    const int lc0  = (tid & 1) * 32;   // byte offset of first chunk (0 or 32)

    auto load_stage = [&](int s, int kb) {
        uint32_t ab = sbase + s * STAGE_B;
        uint32_t bb = ab + TILE_B;
        const char* ga = Ag + (size_t)lrow * rowBytes + (size_t)kb * 64 + lc0;
        const char* gb = Wg + (size_t)lrow * rowBytes + (size_t)kb * 64 + lc0;
        uint32_t da = ab + lrow * LDT_B + lc0;
        uint32_t db = bb + lrow * LDT_B + lc0;
        cp_async16(da,      ga);
        cp_async16(da + 16, ga + 16);
        cp_async16(db,      gb);
        cp_async16(db + 16, gb + 16);
    };

    float acc[2][8][4];
#pragma unroll
    for (int i = 0; i < 2; i++)
#pragma unroll
        for (int j = 0; j < 8; j++)
#pragma unroll
            for (int q = 0; q < 4; q++) acc[i][j][q] = 0.0f;

    // prologue: stages 0..GSTAGES-2
#pragma unroll
    for (int s = 0; s < GSTAGES - 1; s++) {
        if (s < NK) load_stage(s, s);
        cp_commit();
    }

    const int lr16 = lane & 15;
    const int chi  = (lane >> 4) * 16;   // byte offset of k-half (0 or 16)

    for (int i = 0; i < NK; i++) {
        cp_wait<GSTAGES - 2>();
        __syncthreads();

        // issue next stage load (into buffer (i-1)%GSTAGES — safe after sync)
        int nk = i + GSTAGES - 1;
        if (nk < NK) load_stage(nk % GSTAGES, nk);
        cp_commit();

        uint32_t ab = sbase + (i % GSTAGES) * STAGE_B;
        uint32_t bb = ab + TILE_B;

#pragma unroll
        for (int ks = 0; ks < 2; ks++) {
            uint32_t af[2][4], bf[4][4];
#pragma unroll
            for (int i2 = 0; i2 < 2; i2++) {
                uint32_t addr = ab + (wm * 32 + i2 * 16 + lr16) * LDT_B + ks * 32 + chi;
                LDSM_X4(af[i2], addr);
            }
#pragma unroll
            for (int jp = 0; jp < 4; jp++) {
                uint32_t addr = bb + (wn * 64 + jp * 16 + lr16) * LDT_B + ks * 32 + chi;
                LDSM_X4(bf[jp], addr);
            }
#pragma unroll
            for (int i2 = 0; i2 < 2; i2++) {
#pragma unroll
                for (int j = 0; j < 8; j++) {
                    int jp = j >> 1;
                    uint32_t b0 = (j & 1) ? bf[jp][1] : bf[jp][0];
                    uint32_t b1 = (j & 1) ? bf[jp][3] : bf[jp][2];
                    MMA16816(acc[i2][j], af[i2], b0, b1);
                }
            }
        }
        __syncthreads();
    }

    // epilogue
    const int group = lane >> 2, t4 = lane & 3;
#pragma unroll
    for (int i2 = 0; i2 < 2; i2++) {
        int r0 = m0 + wm * 32 + i2 * 16 + group;
#pragma unroll
        for (int j = 0; j < 8; j++) {
            int cidx = n0 + wn * 64 + j * 8 + t4 * 2;
            float bv0 = bias[cidx], bv1 = bias[cidx + 1];
            float2 v0, v1;
            v0.x = acc[i2][j][0] + bv0; v0.y = acc[i2][j][1] + bv1;
            v1.x = acc[i2][j][2] + bv0; v1.y = acc[i2][j][3] + bv1;
            *(float2*)&C[(size_t)r0 * ldc + cidx]       = v0;
            *(float2*)&C[(size_t)(r0 + 8) * ldc + cidx] = v1;
        }
    }
}

// ---------------- recurrent LSTM scan (unchanged, passing) ----------------
template<int H, int NB, int KS, int NREG, int LDXW, bool LAST_ONLY>
__global__ __launch_bounds__(4 * H, 1)
void lstm_kernel(const float* __restrict__ xw,    // [T*B][LDXW], dir off = dir*4H
                 const float* __restrict__ w_hh,  // [dirs][4H][H]
                 float* __restrict__ y)
{
    constexpr int G4 = 4 * H;
    const int g   = threadIdx.x;
    const int dir = blockIdx.y;
    const int b0  = blockIdx.x * NB;

    extern __shared__ float smf[];
    float* Wt    = smf;
    float* hbuf  = Wt + KS * G4;
    float* gates = hbuf + H * NB;

    const float* Wrow = w_hh + (size_t)dir * G4 * H + (size_t)g * H;
    for (int k = 0; k < KS; k++) Wt[k * G4 + g] = Wrow[k];
    float wreg[NREG > 0 ? NREG : 1];
    if constexpr (NREG > 0) {
#pragma unroll
        for (int kk = 0; kk < NREG; kk++) wreg[kk] = Wrow[KS + kk];
    }
    for (int i = g; i < H * NB; i += G4) hbuf[i] = 0.0f;
    float creg = 0.0f;
    __syncthreads();

    const int tstep = (dir == 0) ? 1 : -1;
    int t = (dir == 0) ? 0 : (T_SEQ - 1);

    for (int s = 0; s < T_SEQ; s++, t += tstep) {
        const float* xr = xw + ((size_t)t * B_SZ + b0) * LDXW + dir * G4;
        float acc[NB];
#pragma unroll
        for (int nb = 0; nb < NB; nb++) acc[nb] = xr[(size_t)nb * LDXW + g];

        if constexpr (NB == 4) {
#pragma unroll 8
            for (int k = 0; k < KS; k++) {
                float w = Wt[k * G4 + g];
                float4 h4 = *(const float4*)(hbuf + k * 4);
                acc[0] = fmaf(w, h4.x, acc[0]);
                acc[1] = fmaf(w, h4.y, acc[1]);
                acc[2] = fmaf(w, h4.z, acc[2]);
                acc[3] = fmaf(w, h4.w, acc[3]);
            }
            if constexpr (NREG > 0) {
#pragma unroll
                for (int kk = 0; kk < NREG; kk++) {
                    float4 h4 = *(const float4*)(hbuf + (KS + kk) * 4);
                    acc[0] = fmaf(wreg[kk], h4.x, acc[0]);
                    acc[1] = fmaf(wreg[kk], h4.y, acc[1]);
                    acc[2] = fmaf(wreg[kk], h4.z, acc[2]);
                    acc[3] = fmaf(wreg[kk], h4.w, acc[3]);
                }
            }
        } else {
#pragma unroll 8
            for (int k = 0; k < KS; k++) {
                float w = Wt[k * G4 + g];
                float2 h2 = *(const float2*)(hbuf + k * 2);
                acc[0] = fmaf(w, h2.x, acc[0]);
                acc[1] = fmaf(w, h2.y, acc[1]);
            }
        }

#pragma unroll
        for (int nb = 0; nb < NB; nb++) gates[nb * G4 + g] = acc[nb];
        __syncthreads();

        if (g < NB * H) {
            int nb = g / H, j = g % H;
            const float* gr = gates + nb * G4;
            float xi = gr[j];
            float xf = gr[H + j];
            float xg = gr[2 * H + j];
            float xo = gr[3 * H + j];
            float si = sigf(xi), sf = sigf(xf), so = sigf(xo);
            float tg = tanhf_(xg);
            creg = fmaf(sf, creg, si * tg);
            float h = so * tanhf_(creg);
            hbuf[j * NB + nb] = h;
            if constexpr (LAST_ONLY) {
                if (s == T_SEQ - 1) y[(size_t)(b0 + nb) * 128 + j] = h;
            } else {
                y[((size_t)t * B_SZ + b0 + nb) * 256 + dir * H + j] = h;
            }
        }
        __syncthreads();
    }
}

// ---------------- layer-3 backward: single step from zero state -----------
__global__ void lstm3_bwd_last(const float* __restrict__ xwb, float* __restrict__ h3)
{
    int b = blockIdx.x;
    int j = threadIdx.x;  // 0..63
    const float* gr = xwb + b * 256;
    float xi = gr[j], xg = gr[128 + j], xo = gr[192 + j];
    float c = sigf(xi) * tanhf_(xg);
    float h = sigf(xo) * tanhf_(c);
    h3[b * 128 + 64 + j] = h;
}

// ---------------- small FC ----------------
__global__ void fc_kernel(const float* __restrict__ in, const float* __restrict__ w,
                          const float* __restrict__ bias, float* __restrict__ out,
                          int K, int O, int do_relu)
{
    int b = blockIdx.x;
    extern __shared__ float s_in[];
    for (int k = threadIdx.x; k < K; k += blockDim.x) s_in[k] = in[(size_t)b * K + k];
    __syncthreads();
    for (int o = threadIdx.x; o < O; o += blockDim.x) {
        float acc = bias[o];
        const float* wr = w + (size_t)o * K;
        for (int k = 0; k < K; k++) acc = fmaf(s_in[k], wr[k], acc);
        if (do_relu) acc = fmaxf(acc, 0.0f);
        out[(size_t)b * O + o] = acc;
    }
}

// ---------------- host orchestration --------------------------------------
extern "C" void kernel_launch(void* const* d_in, const int* in_sizes, int n_in,
                              void* d_out, int out_size)
{
    const float* x      = (const float*)d_in[0];
    const float* conv_w = (const float*)d_in[1];
    const float* conv_b = (const float*)d_in[2];
    const float* w_ih1  = (const float*)d_in[3];
    const float* w_hh1  = (const float*)d_in[4];
    const float* b1     = (const float*)d_in[5];
    const float* w_ih2  = (const float*)d_in[6];
    const float* w_hh2  = (const float*)d_in[7];
    const float* b2     = (const float*)d_in[8];
    const float* w_ih3  = (const float*)d_in[9];
    const float* w_hh3  = (const float*)d_in[10];
    const float* b3     = (const float*)d_in[11];
    const float* fc1_w  = (const float*)d_in[12];
    const float* fc1_b  = (const float*)d_in[13];
    const float* fc2_w  = (const float*)d_in[14];
    const float* fc2_b  = (const float*)d_in[15];
    const float* fc3_w  = (const float*)d_in[16];
    const float* fc3_b  = (const float*)d_in[17];
    const float* fc4_w  = (const float*)d_in[18];
    const float* fc4_b  = (const float*)d_in[19];
    float* out = (float*)d_out;

    float *pX0, *pXW, *pY, *pXWB3, *pH3, *pF1, *pF2, *pF3;
    __nv_bfloat16 *pAp, *pWp;
    cudaGetSymbolAddress((void**)&pX0,   g_X0);
    cudaGetSymbolAddress((void**)&pXW,   g_XW);
    cudaGetSymbolAddress((void**)&pY,    g_Y);
    cudaGetSymbolAddress((void**)&pAp,   g_Ap);
    cudaGetSymbolAddress((void**)&pWp,   g_Wp);
    cudaGetSymbolAddress((void**)&pXWB3, g_XWB3);
    cudaGetSymbolAddress((void**)&pH3,   g_H3);
    cudaGetSymbolAddress((void**)&pF1,   g_F1);
    cudaGetSymbolAddress((void**)&pF2,   g_F2);
    cudaGetSymbolAddress((void**)&pF3,   g_F3);

    const int M = T_SEQ * B_SZ;  // 262144

    constexpr int SMEM128 = (104 * 512 + 128 * 4 + 4 * 512) * 4;
    constexpr int SMEM64  = (64 * 256 + 64 * 2 + 2 * 256) * 4;
    cudaFuncSetAttribute(lstm_kernel<128, 4, 104, 24, 1024, false>,
                         cudaFuncAttributeMaxDynamicSharedMemorySize, SMEM128);
    cudaFuncSetAttribute(lstm_kernel<64, 2, 64, 0, 256, true>,
                         cudaFuncAttributeMaxDynamicSharedMemorySize, SMEM64);
    cudaFuncSetAttribute(gemm_mma,
                         cudaFuncAttributeMaxDynamicSharedMemorySize, GSMEM);

    // 1) conv -> X0 [t][b][64]
    conv_kernel<<<dim3(T_SEQ / 4, B_SZ), 256>>>(x, conv_w, conv_b, pX0);

    // 2) layer 1: split (K=64 -> K'=192) + HMMA GEMM, N=1024
    {
        int t2a = M * 32;
        split2_kernel<<<(t2a + 255) / 256, 256>>>(pX0, pAp, t2a, 32, 64, 0);
        int t2w = 1024 * 32;
        split2_kernel<<<(t2w + 255) / 256, 256>>>(w_ih1, pWp, t2w, 32, 64, 1);
        gemm_mma<<<dim3(8, M / 128), 256, GSMEM>>>(pAp, pWp, b1, pXW, 192, 1024);
    }
    lstm_kernel<128, 4, 104, 24, 1024, false>
        <<<dim3(B_SZ / 4, 2), 512, SMEM128>>>(pXW, w_hh1, pY);

    // 3) layer 2: K=256 -> K'=768
    {
        int t2a = M * 128;
        split2_kernel<<<(t2a + 255) / 256, 256>>>(pY, pAp, t2a, 128, 256, 0);
        int t2w = 1024 * 128;
        split2_kernel<<<(t2w + 255) / 256, 256>>>(w_ih2, pWp, t2w, 128, 256, 1);
        gemm_mma<<<dim3(8, M / 128), 256, GSMEM>>>(pAp, pWp, b2, pXW, 768, 1024);
    }
    lstm_kernel<128, 4, 104, 24, 1024, false>
        <<<dim3(B_SZ / 4, 2), 512, SMEM128>>>(pXW, w_hh2, pY);

    // 4) layer 3 forward: N=256 (fwd dir rows of W'), full scan keep last h
    {
        int t2a = M * 128;
        split2_kernel<<<(t2a + 255) / 256, 256>>>(pY, pAp, t2a, 128, 256, 0);
        int t2w = 512 * 128;
        split2_kernel<<<(t2w + 255) / 256, 256>>>(w_ih3, pWp, t2w, 128, 256, 1);
        gemm_mma<<<dim3(2, M / 128), 256, GSMEM>>>(pAp, pWp, b3, pXW, 768, 256);
    }
    lstm_kernel<64, 2, 64, 0, 256, true>
        <<<dim3(B_SZ / 2, 1), 256, SMEM64>>>(pXW, w_hh3, pH3);

    // 5) layer 3 backward at t=T-1 only: one step from zero state
    gemm_mma<<<dim3(2, 2), 256, GSMEM>>>(
        pAp + (size_t)(T_SEQ - 1) * B_SZ * 768,
        pWp + (size_t)256 * 768, b3 + 256, pXWB3, 768, 256);
    lstm3_bwd_last<<<B_SZ, 64>>>(pXWB3, pH3);

    // 6) FC head
    fc_kernel<<<B_SZ, 128, 128 * 4>>>(pH3, fc1_w, fc1_b, pF1, 128, 512, 1);
    fc_kernel<<<B_SZ, 128, 512 * 4>>>(pF1, fc2_w, fc2_b, pF2, 512, 256, 1);
    fc_kernel<<<B_SZ, 128, 256 * 4>>>(pF2, fc3_w, fc3_b, pF3, 256, 128, 1);
    fc_kernel<<<B_SZ, 64, 128 * 4>>>(pF3, fc4_w, fc4_b, out, 128, 2, 0);

    (void)in_sizes; (void)n_in; (void)out_size;
}

// round 8
// speedup vs baseline: 1.3440x; 1.1557x over previous
#include <cuda_runtime.h>
#include <cuda_bf16.h>
#include <cstdint>

#define T_SEQ 1024
#define B_SZ  256

// ---------------- device scratch (allocation-free statics) ----------------
__device__ float g_XW[262144ull * 1024];            // xw fp32 [t*B+b][<=1024]
__device__ __nv_bfloat16 g_Ap[262144ull * 768];     // split-bf16 A' [row][3K]
__device__ __nv_bfloat16 g_Wp[1024ull * 768];       // split-bf16 W' [row][3K]
__device__ float g_XWB3[256 * 256];
__device__ float g_H3[256 * 128];
__device__ float g_F1[256 * 512];
__device__ float g_F2[256 * 256];
__device__ float g_F3[256 * 128];

// ---------------- portable PTX helpers ----------------
__device__ __forceinline__ uint32_t smem_to_u32(const void* p) {
    uint32_t a;
    asm("{ .reg .u64 t; cvta.to.shared.u64 t, %1; cvt.u32.u64 %0, t; }" : "=r"(a) : "l"(p));
    return a;
}
__device__ __forceinline__ void cp_async16(uint32_t dst, const void* src) {
    asm volatile("cp.async.cg.shared.global [%0], [%1], 16;" :: "r"(dst), "l"(src) : "memory");
}
__device__ __forceinline__ void cp_commit() {
    asm volatile("cp.async.commit_group;" ::: "memory");
}
template<int N>
__device__ __forceinline__ void cp_wait() {
    asm volatile("cp.async.wait_group %0;" :: "n"(N) : "memory");
}
#define LDSM_X4(r, addr) \
    asm volatile("ldmatrix.sync.aligned.m8n8.x4.shared.b16 {%0,%1,%2,%3}, [%4];" \
        : "=r"((r)[0]), "=r"((r)[1]), "=r"((r)[2]), "=r"((r)[3]) : "r"(addr))
#define MMA16816(d, a, b0, b1) \
    asm volatile("mma.sync.aligned.m16n8k16.row.col.f32.bf16.bf16.f32 " \
        "{%0,%1,%2,%3}, {%4,%5,%6,%7}, {%8,%9}, {%0,%1,%2,%3};" \
        : "+f"((d)[0]), "+f"((d)[1]), "+f"((d)[2]), "+f"((d)[3]) \
        : "r"((a)[0]), "r"((a)[1]), "r"((a)[2]), "r"((a)[3]), "r"(b0), "r"(b1))

// packed fp32x2 FMA (Blackwell dual-lane fp32): d = a*b + d, lanewise
__device__ __forceinline__ void fma2(uint64_t& d, uint64_t a, uint64_t b) {
    asm("fma.rn.f32x2 %0, %1, %2, %0;" : "+l"(d) : "l"(a), "l"(b));
}
__device__ __forceinline__ uint64_t pack_dup(float w) {
    uint64_t r;
    asm("mov.b64 %0, {%1, %1};" : "=l"(r) : "f"(w));
    return r;
}
__device__ __forceinline__ uint64_t pack2(float a, float b) {
    uint64_t r;
    asm("mov.b64 %0, {%1, %2};" : "=l"(r) : "f"(a), "f"(b));
    return r;
}
__device__ __forceinline__ void unpack2(uint64_t v, float& a, float& b) {
    asm("mov.b64 {%0, %1}, %2;" : "=f"(a), "=f"(b) : "l"(v));
}
// VOLATILE shared loads of h (must re-read every timestep; non-volatile asm
// with register-only outputs was CSE'd across the scan loop in R7 -> stale h)
__device__ __forceinline__ void lds_v2u64(uint64_t& a, uint64_t& b, uint32_t addr) {
    asm volatile("ld.shared.v2.u64 {%0,%1}, [%2];" : "=l"(a), "=l"(b) : "r"(addr));
}

// ---------------- activations ----------------
__device__ __forceinline__ float sigf(float x) {
    return __fdividef(1.0f, 1.0f + __expf(-x));
}
__device__ __forceinline__ float tanhf_(float x) {
    return __fdividef(2.0f, 1.0f + __expf(-2.0f * x)) - 1.0f;
}

// ---------------- conv1d (causal k=5, 1->64) + relu + fused bf16 split -----
// writes A' rows [t*B+b][192] = [hi(64) | hi(64) | lo(64)]
__global__ void conv_kernel(const float* __restrict__ x, const float* __restrict__ w,
                            const float* __restrict__ bias, __nv_bfloat16* __restrict__ ap)
{
    int tid = threadIdx.x;            // 256
    int c   = tid & 63;
    int ts  = tid >> 6;
    int t   = blockIdx.x * 4 + ts;
    int b   = blockIdx.y;
    float acc = bias[c];
#pragma unroll
    for (int k = 0; k < 5; k++) {
        int xi = t - 4 + k;
        float xv = (xi >= 0) ? x[(size_t)b * T_SEQ + xi] : 0.0f;
        acc = fmaf(xv, w[c * 5 + k], acc);
    }
    float v = fmaxf(acc, 0.0f);
    __nv_bfloat16 hi = __float2bfloat16(v);
    __nv_bfloat16 lo = __float2bfloat16(v - __bfloat162float(hi));
    size_t base = ((size_t)t * B_SZ + b) * 192;
    ap[base + c]       = hi;
    ap[base + 64 + c]  = hi;
    ap[base + 128 + c] = lo;
}

// ---------------- split fp32 -> bf16 along K (weights only) ---------------
// W pattern: [hi, lo, hi]
__global__ void split2_kernel(const float* __restrict__ src, __nv_bfloat16* __restrict__ dst,
                              int total2, int Khalf, int K)
{
    int i = blockIdx.x * blockDim.x + threadIdx.x;
    if (i >= total2) return;
    int r = i / Khalf;
    int k = (i - r * Khalf) * 2;
    float2 v = *(const float2*)(src + (size_t)r * K + k);
    __nv_bfloat16 hx = __float2bfloat16(v.x);
    __nv_bfloat16 hy = __float2bfloat16(v.y);
    __nv_bfloat16 lx = __float2bfloat16(v.x - __bfloat162float(hx));
    __nv_bfloat16 ly = __float2bfloat16(v.y - __bfloat162float(hy));
    __nv_bfloat162 hi; hi.x = hx; hi.y = hy;
    __nv_bfloat162 lo; lo.x = lx; lo.y = ly;
    __nv_bfloat16* d = dst + (size_t)r * 3 * K + k;
    *(__nv_bfloat162*)(d)         = hi;
    *(__nv_bfloat162*)(d + K)     = lo;
    *(__nv_bfloat162*)(d + 2 * K) = hi;
}

// ---------------- HMMA GEMM (unchanged, passing) ---------------------------
#define GSTAGES 4
#define LDT_B   80
#define TILE_B  (128 * LDT_B)
#define STAGE_B (2 * TILE_B)
#define GSMEM   (GSTAGES * STAGE_B)

__global__ __launch_bounds__(256)
void gemm_mma(const __nv_bfloat16* __restrict__ A, const __nv_bfloat16* __restrict__ W,
              const float* __restrict__ bias, float* __restrict__ C,
              int Kp, int ldc)
{
    extern __shared__ char sm[];
    const uint32_t sbase = smem_to_u32(sm);
    const int tid  = threadIdx.x;
    const int wid  = tid >> 5, lane = tid & 31;
    const int wm   = wid & 3;
    const int wn   = wid >> 2;
    const int n0   = blockIdx.x * 128;
    const int m0   = blockIdx.y * 128;
    const int NK   = Kp >> 5;
    const size_t rowBytes = (size_t)Kp * 2;

    const char* Ag = (const char*)(A + (size_t)m0 * Kp);
    const char* Wg = (const char*)(W + (size_t)n0 * Kp);

    const int lrow = tid >> 1;
    const int lc0  = (tid & 1) * 32;

    auto load_stage = [&](int s, int kb) {
        uint32_t ab = sbase + s * STAGE_B;
        uint32_t bb = ab + TILE_B;
        const char* ga = Ag + (size_t)lrow * rowBytes + (size_t)kb * 64 + lc0;
        const char* gb = Wg + (size_t)lrow * rowBytes + (size_t)kb * 64 + lc0;
        uint32_t da = ab + lrow * LDT_B + lc0;
        uint32_t db = bb + lrow * LDT_B + lc0;
        cp_async16(da,      ga);
        cp_async16(da + 16, ga + 16);
        cp_async16(db,      gb);
        cp_async16(db + 16, gb + 16);
    };

    float acc[2][8][4];
#pragma unroll
    for (int i = 0; i < 2; i++)
#pragma unroll
        for (int j = 0; j < 8; j++)
#pragma unroll
            for (int q = 0; q < 4; q++) acc[i][j][q] = 0.0f;

#pragma unroll
    for (int s = 0; s < GSTAGES - 1; s++) {
        if (s < NK) load_stage(s, s);
        cp_commit();
    }

    const int lr16 = lane & 15;
    const int chi  = (lane >> 4) * 16;

    for (int i = 0; i < NK; i++) {
        cp_wait<GSTAGES - 2>();
        __syncthreads();

        int nk = i + GSTAGES - 1;
        if (nk < NK) load_stage(nk % GSTAGES, nk);
        cp_commit();

        uint32_t ab = sbase + (i % GSTAGES) * STAGE_B;
        uint32_t bb = ab + TILE_B;

#pragma unroll
        for (int ks = 0; ks < 2; ks++) {
            uint32_t af[2][4], bf[4][4];
#pragma unroll
            for (int i2 = 0; i2 < 2; i2++) {
                uint32_t addr = ab + (wm * 32 + i2 * 16 + lr16) * LDT_B + ks * 32 + chi;
                LDSM_X4(af[i2], addr);
            }
#pragma unroll
            for (int jp = 0; jp < 4; jp++) {
                uint32_t addr = bb + (wn * 64 + jp * 16 + lr16) * LDT_B + ks * 32 + chi;
                LDSM_X4(bf[jp], addr);
            }
#pragma unroll
            for (int i2 = 0; i2 < 2; i2++) {
#pragma unroll
                for (int j = 0; j < 8; j++) {
                    int jp = j >> 1;
                    uint32_t b0 = (j & 1) ? bf[jp][1] : bf[jp][0];
                    uint32_t b1 = (j & 1) ? bf[jp][3] : bf[jp][2];
                    MMA16816(acc[i2][j], af[i2], b0, b1);
                }
            }
        }
        __syncthreads();
    }

    const int group = lane >> 2, t4 = lane & 3;
#pragma unroll
    for (int i2 = 0; i2 < 2; i2++) {
        int r0 = m0 + wm * 32 + i2 * 16 + group;
#pragma unroll
        for (int j = 0; j < 8; j++) {
            int cidx = n0 + wn * 64 + j * 8 + t4 * 2;
            float bv0 = bias[cidx], bv1 = bias[cidx + 1];
            float2 v0, v1;
            v0.x = acc[i2][j][0] + bv0; v0.y = acc[i2][j][1] + bv1;
            v1.x = acc[i2][j][2] + bv0; v1.y = acc[i2][j][3] + bv1;
            *(float2*)&C[(size_t)r0 * ldc + cidx]       = v0;
            *(float2*)&C[(size_t)(r0 + 8) * ldc + cidx] = v1;
        }
    }
}

// ---------------- recurrent LSTM scan v2 (volatile h loads) ----------------
// Block = 4H threads (one per gate column). CTA = NB batch rows, one dir.
// f32x2 packed FMA; W as float2 pairs over k in smem + NREG reg-resident rows;
// h read via volatile ld.shared.v2.u64 broadcast; xw prefetched one step ahead.
// KOUT>0: write split-bf16 A' rows [row][KOUT]; KOUT==0: write h3 at last step.
template<int H, int NB, int KS, int NREG, int LDXW, int KOUT>
__global__ __launch_bounds__(4 * H, 1)
void lstm_scan(const float* __restrict__ xw, const float* __restrict__ w_hh,
               __nv_bfloat16* __restrict__ ap, float* __restrict__ h3out)
{
    constexpr int G4 = 4 * H;
    const int g   = threadIdx.x;
    const int dir = blockIdx.y;
    const int b0  = blockIdx.x * NB;

    extern __shared__ float smf[];
    float2* Wt2  = (float2*)smf;              // [KS/2][G4]
    float*  hbuf = smf + KS * G4;             // [H][NB]
    float*  gates = hbuf + H * NB;            // [NB][G4]

    const float* Wrow = w_hh + (size_t)dir * G4 * H + (size_t)g * H;
    for (int k2 = 0; k2 < KS / 2; k2++) {
        float2 w2;
        w2.x = Wrow[2 * k2];
        w2.y = Wrow[2 * k2 + 1];
        Wt2[k2 * G4 + g] = w2;
    }
    uint64_t wwreg[NREG > 0 ? NREG : 1];
    if constexpr (NREG > 0) {
#pragma unroll
        for (int kk = 0; kk < NREG; kk++) wwreg[kk] = pack_dup(Wrow[KS + kk]);
    }
    for (int i = g; i < H * NB; i += G4) hbuf[i] = 0.0f;
    float creg = 0.0f;
    __syncthreads();

    const uint32_t hb = smem_to_u32(hbuf);
    const int tstep = dir ? -1 : 1;
    int t = dir ? (T_SEQ - 1) : 0;
    const ptrdiff_t xstep = (ptrdiff_t)tstep * B_SZ * LDXW;
    const float* xr = xw + ((size_t)t * B_SZ + b0) * LDXW + dir * G4 + g;

    float nx[NB];
#pragma unroll
    for (int nb = 0; nb < NB; nb++) nx[nb] = xr[(size_t)nb * LDXW];

    for (int s = 0; s < T_SEQ; s++, t += tstep) {
        uint64_t acc01 = pack2(nx[0], nx[1]);
        uint64_t acc23 = 0;
        if constexpr (NB == 4) acc23 = pack2(nx[2], nx[3]);

        // prefetch next step's xw (hidden under FMA loop)
        if (s + 1 < T_SEQ) {
            xr += xstep;
#pragma unroll
            for (int nb = 0; nb < NB; nb++) nx[nb] = xr[(size_t)nb * LDXW];
        }

#pragma unroll 4
        for (int k2 = 0; k2 < KS / 2; k2++) {
            float2 w2 = Wt2[k2 * G4 + g];
            uint64_t ww0 = pack_dup(w2.x);
            uint64_t ww1 = pack_dup(w2.y);
            if constexpr (NB == 4) {
                uint64_t h01a, h23a, h01b, h23b;
                lds_v2u64(h01a, h23a, hb + k2 * 32);
                lds_v2u64(h01b, h23b, hb + k2 * 32 + 16);
                fma2(acc01, ww0, h01a); fma2(acc23, ww0, h23a);
                fma2(acc01, ww1, h01b); fma2(acc23, ww1, h23b);
            } else {
                uint64_t ha, hbv;
                lds_v2u64(ha, hbv, hb + k2 * 16);
                fma2(acc01, ww0, ha);
                fma2(acc01, ww1, hbv);
            }
        }
        if constexpr (NREG > 0) {
#pragma unroll
            for (int kk2 = 0; kk2 < NREG / 2; kk2++) {
                uint64_t h01a, h23a, h01b, h23b;
                lds_v2u64(h01a, h23a, hb + (KS / 2 + kk2) * 32);
                lds_v2u64(h01b, h23b, hb + (KS / 2 + kk2) * 32 + 16);
                fma2(acc01, wwreg[2 * kk2],     h01a);
                fma2(acc23, wwreg[2 * kk2],     h23a);
                fma2(acc01, wwreg[2 * kk2 + 1], h01b);
                fma2(acc23, wwreg[2 * kk2 + 1], h23b);
            }
        }

        float a0, a1;
        unpack2(acc01, a0, a1);
        gates[0 * G4 + g] = a0;
        gates[1 * G4 + g] = a1;
        if constexpr (NB == 4) {
            float a2, a3;
            unpack2(acc23, a2, a3);
            gates[2 * G4 + g] = a2;
            gates[3 * G4 + g] = a3;
        }
        __syncthreads();

        if (g < NB * H) {
            const int nb = g / H, j = g - nb * H;
            const float* gr = gates + nb * G4;
            float xi = gr[j];
            float xf = gr[H + j];
            float xg = gr[2 * H + j];
            float xo = gr[3 * H + j];
            float si = sigf(xi), sf = sigf(xf), so = sigf(xo);
            float tg = tanhf_(xg);
            creg = fmaf(sf, creg, si * tg);
            float h = so * tanhf_(creg);
            hbuf[j * NB + nb] = h;
            if constexpr (KOUT > 0) {
                // fused bf16 split write: A'[row] = [hi | hi | lo], K = KOUT/3
                __nv_bfloat16 hi = __float2bfloat16(h);
                __nv_bfloat16 lo = __float2bfloat16(h - __bfloat162float(hi));
                size_t base = ((size_t)t * B_SZ + b0 + nb) * KOUT;
                int col = dir * H + j;
                ap[base + col]                  = hi;
                ap[base + (KOUT / 3) + col]     = hi;
                ap[base + 2 * (KOUT / 3) + col] = lo;
            } else {
                if (s == T_SEQ - 1) h3out[(size_t)(b0 + nb) * 128 + j] = h;
            }
        }
        __syncthreads();
    }
}

// ---------------- layer-3 backward: single step from zero state -----------
__global__ void lstm3_bwd_last(const float* __restrict__ xwb, float* __restrict__ h3)
{
    int b = blockIdx.x;
    int j = threadIdx.x;  // 0..63
    const float* gr = xwb + b * 256;
    float xi = gr[j], xg = gr[128 + j], xo = gr[192 + j];
    float c = sigf(xi) * tanhf_(xg);
    float h = sigf(xo) * tanhf_(c);
    h3[b * 128 + 64 + j] = h;
}

// ---------------- small FC ----------------
__global__ void fc_kernel(const float* __restrict__ in, const float* __restrict__ w,
                          const float* __restrict__ bias, float* __restrict__ out,
                          int K, int O, int do_relu)
{
    int b = blockIdx.x;
    extern __shared__ float s_in[];
    for (int k = threadIdx.x; k < K; k += blockDim.x) s_in[k] = in[(size_t)b * K + k];
    __syncthreads();
    for (int o = threadIdx.x; o < O; o += blockDim.x) {
        float acc = bias[o];
        const float* wr = w + (size_t)o * K;
        for (int k = 0; k < K; k++) acc = fmaf(s_in[k], wr[k], acc);
        if (do_relu) acc = fmaxf(acc, 0.0f);
        out[(size_t)b * O + o] = acc;
    }
}

// ---------------- host orchestration --------------------------------------
extern "C" void kernel_launch(void* const* d_in, const int* in_sizes, int n_in,
                              void* d_out, int out_size)
{
    const float* x      = (const float*)d_in[0];
    const float* conv_w = (const float*)d_in[1];
    const float* conv_b = (const float*)d_in[2];
    const float* w_ih1  = (const float*)d_in[3];
    const float* w_hh1  = (const float*)d_in[4];
    const float* b1     = (const float*)d_in[5];
    const float* w_ih2  = (const float*)d_in[6];
    const float* w_hh2  = (const float*)d_in[7];
    const float* b2     = (const float*)d_in[8];
    const float* w_ih3  = (const float*)d_in[9];
    const float* w_hh3  = (const float*)d_in[10];
    const float* b3     = (const float*)d_in[11];
    const float* fc1_w  = (const float*)d_in[12];
    const float* fc1_b  = (const float*)d_in[13];
    const float* fc2_w  = (const float*)d_in[14];
    const float* fc2_b  = (const float*)d_in[15];
    const float* fc3_w  = (const float*)d_in[16];
    const float* fc3_b  = (const float*)d_in[17];
    const float* fc4_w  = (const float*)d_in[18];
    const float* fc4_b  = (const float*)d_in[19];
    float* out = (float*)d_out;

    float *pXW, *pXWB3, *pH3, *pF1, *pF2, *pF3;
    __nv_bfloat16 *pAp, *pWp;
    cudaGetSymbolAddress((void**)&pXW,   g_XW);
    cudaGetSymbolAddress((void**)&pAp,   g_Ap);
    cudaGetSymbolAddress((void**)&pWp,   g_Wp);
    cudaGetSymbolAddress((void**)&pXWB3, g_XWB3);
    cudaGetSymbolAddress((void**)&pH3,   g_H3);
    cudaGetSymbolAddress((void**)&pF1,   g_F1);
    cudaGetSymbolAddress((void**)&pF2,   g_F2);
    cudaGetSymbolAddress((void**)&pF3,   g_F3);

    const int M = T_SEQ * B_SZ;  // 262144

    constexpr int SMEM128 = (104 * 512 + 128 * 4 + 4 * 512) * 4;  // 223232
    constexpr int SMEM64  = (64 * 256 + 64 * 2 + 2 * 256) * 4;    //  68096
    cudaFuncSetAttribute(lstm_scan<128, 4, 104, 24, 1024, 768>,
                         cudaFuncAttributeMaxDynamicSharedMemorySize, SMEM128);
    cudaFuncSetAttribute(lstm_scan<64, 2, 64, 0, 256, 0>,
                         cudaFuncAttributeMaxDynamicSharedMemorySize, SMEM64);
    cudaFuncSetAttribute(gemm_mma,
                         cudaFuncAttributeMaxDynamicSharedMemorySize, GSMEM);

    // 1) conv -> A' [t*B+b][192] (fused bf16 split)
    conv_kernel<<<dim3(T_SEQ / 4, B_SZ), 256>>>(x, conv_w, conv_b, pAp);

    // 2) layer 1: W split (K=64 -> 192) + GEMM + scan (scan writes A'[768])
    split2_kernel<<<(1024 * 32 + 255) / 256, 256>>>(w_ih1, pWp, 1024 * 32, 32, 64);
    gemm_mma<<<dim3(8, M / 128), 256, GSMEM>>>(pAp, pWp, b1, pXW, 192, 1024);
    lstm_scan<128, 4, 104, 24, 1024, 768>
        <<<dim3(B_SZ / 4, 2), 512, SMEM128>>>(pXW, w_hh1, pAp, nullptr);

    // 3) layer 2: K=256 -> 768
    split2_kernel<<<(1024 * 128 + 255) / 256, 256>>>(w_ih2, pWp, 1024 * 128, 128, 256);
    gemm_mma<<<dim3(8, M / 128), 256, GSMEM>>>(pAp, pWp, b2, pXW, 768, 1024);
    lstm_scan<128, 4, 104, 24, 1024, 768>
        <<<dim3(B_SZ / 4, 2), 512, SMEM128>>>(pXW, w_hh2, pAp, nullptr);

    // 4) layer 3 forward: N=256 (fwd gates only), full scan, keep last h
    split2_kernel<<<(512 * 128 + 255) / 256, 256>>>(w_ih3, pWp, 512 * 128, 128, 256);
    gemm_mma<<<dim3(2, M / 128), 256, GSMEM>>>(pAp, pWp, b3, pXW, 768, 256);
    lstm_scan<64, 2, 64, 0, 256, 0>
        <<<dim3(B_SZ / 2, 1), 256, SMEM64>>>(pXW, w_hh3, nullptr, pH3);

    // 5) layer 3 backward at t=T-1 only: one step from zero state
    gemm_mma<<<dim3(2, 2), 256, GSMEM>>>(
        pAp + (size_t)(T_SEQ - 1) * B_SZ * 768,
        pWp + (size_t)256 * 768, b3 + 256, pXWB3, 768, 256);
    lstm3_bwd_last<<<B_SZ, 64>>>(pXWB3, pH3);

    // 6) FC head
    fc_kernel<<<B_SZ, 128, 128 * 4>>>(pH3, fc1_w, fc1_b, pF1, 128, 512, 1);
    fc_kernel<<<B_SZ, 128, 512 * 4>>>(pF1, fc2_w, fc2_b, pF2, 512, 256, 1);
    fc_kernel<<<B_SZ, 128, 256 * 4>>>(pF2, fc3_w, fc3_b, pF3, 256, 128, 1);
    fc_kernel<<<B_SZ, 64, 128 * 4>>>(pF3, fc4_w, fc4_b, out, 128, 2, 0);

    (void)in_sizes; (void)n_in; (void)out_size;
}

// round 9
// speedup vs baseline: 1.6157x; 1.2022x over previous
#include <cuda_runtime.h>
#include <cuda_bf16.h>
#include <cstdint>

#define T_SEQ 1024
#define B_SZ  256

// ---------------- device scratch (allocation-free statics) ----------------
__device__ float g_XW[262144ull * 1024];            // xw fp32 [t*B+b][<=1024]
__device__ __nv_bfloat16 g_Ap[262144ull * 768];     // split-bf16 A' [row][3K]
__device__ __nv_bfloat16 g_Wp[1024ull * 768];       // split-bf16 W' [row][3K]
__device__ float g_XWB3[256 * 256];
__device__ float g_H3[256 * 128];
__device__ float g_F1[256 * 512];
__device__ float g_F2[256 * 256];
__device__ float g_F3[256 * 128];

// ---------------- portable PTX helpers ----------------
__device__ __forceinline__ uint32_t smem_to_u32(const void* p) {
    uint32_t a;
    asm("{ .reg .u64 t; cvta.to.shared.u64 t, %1; cvt.u32.u64 %0, t; }" : "=r"(a) : "l"(p));
    return a;
}
__device__ __forceinline__ void cp_async16(uint32_t dst, const void* src) {
    asm volatile("cp.async.cg.shared.global [%0], [%1], 16;" :: "r"(dst), "l"(src) : "memory");
}
__device__ __forceinline__ void cp_commit() {
    asm volatile("cp.async.commit_group;" ::: "memory");
}
template<int N>
__device__ __forceinline__ void cp_wait() {
    asm volatile("cp.async.wait_group %0;" :: "n"(N) : "memory");
}
#define LDSM_X4(r, addr) \
    asm volatile("ldmatrix.sync.aligned.m8n8.x4.shared.b16 {%0,%1,%2,%3}, [%4];" \
        : "=r"((r)[0]), "=r"((r)[1]), "=r"((r)[2]), "=r"((r)[3]) : "r"(addr))
#define MMA16816(d, a, b0, b1) \
    asm volatile("mma.sync.aligned.m16n8k16.row.col.f32.bf16.bf16.f32 " \
        "{%0,%1,%2,%3}, {%4,%5,%6,%7}, {%8,%9}, {%0,%1,%2,%3};" \
        : "+f"((d)[0]), "+f"((d)[1]), "+f"((d)[2]), "+f"((d)[3]) \
        : "r"((a)[0]), "r"((a)[1]), "r"((a)[2]), "r"((a)[3]), "r"(b0), "r"(b1))

// packed fp32x2 FMA (Blackwell dual-lane fp32): d = a*b + d, lanewise
__device__ __forceinline__ void fma2(uint64_t& d, uint64_t a, uint64_t b) {
    asm("fma.rn.f32x2 %0, %1, %2, %0;" : "+l"(d) : "l"(a), "l"(b));
}
__device__ __forceinline__ uint64_t pack_dup(float w) {
    uint64_t r;
    asm("mov.b64 %0, {%1, %1};" : "=l"(r) : "f"(w));
    return r;
}
__device__ __forceinline__ uint64_t pack2(float a, float b) {
    uint64_t r;
    asm("mov.b64 %0, {%1, %2};" : "=l"(r) : "f"(a), "f"(b));
    return r;
}
__device__ __forceinline__ void unpack2(uint64_t v, float& a, float& b) {
    asm("mov.b64 {%0, %1}, %2;" : "=f"(a), "=f"(b) : "l"(v));
}
__device__ __forceinline__ float hadd2(uint64_t v) {
    float a, b; unpack2(v, a, b); return a + b;
}
// volatile LDS (used only by the legacy H=64 scan kernel)
__device__ __forceinline__ void lds_v2u64(uint64_t& a, uint64_t& b, uint32_t addr) {
    asm volatile("ld.shared.v2.u64 {%0,%1}, [%2];" : "=l"(a), "=l"(b) : "r"(addr));
}

// ---------------- activations ----------------
__device__ __forceinline__ float sigf(float x) {
    return __fdividef(1.0f, 1.0f + __expf(-x));
}
__device__ __forceinline__ float tanhf_(float x) {
    return __fdividef(2.0f, 1.0f + __expf(-2.0f * x)) - 1.0f;
}

// ---------------- conv1d (causal k=5, 1->64) + relu + fused bf16 split -----
__global__ void conv_kernel(const float* __restrict__ x, const float* __restrict__ w,
                            const float* __restrict__ bias, __nv_bfloat16* __restrict__ ap)
{
    int tid = threadIdx.x;            // 256
    int c   = tid & 63;
    int ts  = tid >> 6;
    int t   = blockIdx.x * 4 + ts;
    int b   = blockIdx.y;
    float acc = bias[c];
#pragma unroll
    for (int k = 0; k < 5; k++) {
        int xi = t - 4 + k;
        float xv = (xi >= 0) ? x[(size_t)b * T_SEQ + xi] : 0.0f;
        acc = fmaf(xv, w[c * 5 + k], acc);
    }
    float v = fmaxf(acc, 0.0f);
    __nv_bfloat16 hi = __float2bfloat16(v);
    __nv_bfloat16 lo = __float2bfloat16(v - __bfloat162float(hi));
    size_t base = ((size_t)t * B_SZ + b) * 192;
    ap[base + c]       = hi;
    ap[base + 64 + c]  = hi;
    ap[base + 128 + c] = lo;
}

// ---------------- split fp32 -> bf16 along K (weights only) ---------------
__global__ void split2_kernel(const float* __restrict__ src, __nv_bfloat16* __restrict__ dst,
                              int total2, int Khalf, int K)
{
    int i = blockIdx.x * blockDim.x + threadIdx.x;
    if (i >= total2) return;
    int r = i / Khalf;
    int k = (i - r * Khalf) * 2;
    float2 v = *(const float2*)(src + (size_t)r * K + k);
    __nv_bfloat16 hx = __float2bfloat16(v.x);
    __nv_bfloat16 hy = __float2bfloat16(v.y);
    __nv_bfloat16 lx = __float2bfloat16(v.x - __bfloat162float(hx));
    __nv_bfloat16 ly = __float2bfloat16(v.y - __bfloat162float(hy));
    __nv_bfloat162 hi; hi.x = hx; hi.y = hy;
    __nv_bfloat162 lo; lo.x = lx; lo.y = ly;
    __nv_bfloat16* d = dst + (size_t)r * 3 * K + k;
    *(__nv_bfloat162*)(d)         = hi;
    *(__nv_bfloat162*)(d + K)     = lo;
    *(__nv_bfloat162*)(d + 2 * K) = hi;
}

// ---------------- HMMA GEMM (unchanged, passing) ---------------------------
#define GSTAGES 4
#define LDT_B   80
#define TILE_B  (128 * LDT_B)
#define STAGE_B (2 * TILE_B)
#define GSMEM   (GSTAGES * STAGE_B)

__global__ __launch_bounds__(256)
void gemm_mma(const __nv_bfloat16* __restrict__ A, const __nv_bfloat16* __restrict__ W,
              const float* __restrict__ bias, float* __restrict__ C,
              int Kp, int ldc)
{
    extern __shared__ char sm[];
    const uint32_t sbase = smem_to_u32(sm);
    const int tid  = threadIdx.x;
    const int wid  = tid >> 5, lane = tid & 31;
    const int wm   = wid & 3;
    const int wn   = wid >> 2;
    const int n0   = blockIdx.x * 128;
    const int m0   = blockIdx.y * 128;
    const int NK   = Kp >> 5;
    const size_t rowBytes = (size_t)Kp * 2;

    const char* Ag = (const char*)(A + (size_t)m0 * Kp);
    const char* Wg = (const char*)(W + (size_t)n0 * Kp);

    const int lrow = tid >> 1;
    const int lc0  = (tid & 1) * 32;

    auto load_stage = [&](int s, int kb) {
        uint32_t ab = sbase + s * STAGE_B;
        uint32_t bb = ab + TILE_B;
        const char* ga = Ag + (size_t)lrow * rowBytes + (size_t)kb * 64 + lc0;
        const char* gb = Wg + (size_t)lrow * rowBytes + (size_t)kb * 64 + lc0;
        uint32_t da = ab + lrow * LDT_B + lc0;
        uint32_t db = bb + lrow * LDT_B + lc0;
        cp_async16(da,      ga);
        cp_async16(da + 16, ga + 16);
        cp_async16(db,      gb);
        cp_async16(db + 16, gb + 16);
    };

    float acc[2][8][4];
#pragma unroll
    for (int i = 0; i < 2; i++)
#pragma unroll
        for (int j = 0; j < 8; j++)
#pragma unroll
            for (int q = 0; q < 4; q++) acc[i][j][q] = 0.0f;

#pragma unroll
    for (int s = 0; s < GSTAGES - 1; s++) {
        if (s < NK) load_stage(s, s);
        cp_commit();
    }

    const int lr16 = lane & 15;
    const int chi  = (lane >> 4) * 16;

    for (int i = 0; i < NK; i++) {
        cp_wait<GSTAGES - 2>();
        __syncthreads();

        int nk = i + GSTAGES - 1;
        if (nk < NK) load_stage(nk % GSTAGES, nk);
        cp_commit();

        uint32_t ab = sbase + (i % GSTAGES) * STAGE_B;
        uint32_t bb = ab + TILE_B;

#pragma unroll
        for (int ks = 0; ks < 2; ks++) {
            uint32_t af[2][4], bf[4][4];
#pragma unroll
            for (int i2 = 0; i2 < 2; i2++) {
                uint32_t addr = ab + (wm * 32 + i2 * 16 + lr16) * LDT_B + ks * 32 + chi;
                LDSM_X4(af[i2], addr);
            }
#pragma unroll
            for (int jp = 0; jp < 4; jp++) {
                uint32_t addr = bb + (wn * 64 + jp * 16 + lr16) * LDT_B + ks * 32 + chi;
                LDSM_X4(bf[jp], addr);
            }
#pragma unroll
            for (int i2 = 0; i2 < 2; i2++) {
#pragma unroll
                for (int j = 0; j < 8; j++) {
                    int jp = j >> 1;
                    uint32_t b0 = (j & 1) ? bf[jp][1] : bf[jp][0];
                    uint32_t b1 = (j & 1) ? bf[jp][3] : bf[jp][2];
                    MMA16816(acc[i2][j], af[i2], b0, b1);
                }
            }
        }
        __syncthreads();
    }

    const int group = lane >> 2, t4 = lane & 3;
#pragma unroll
    for (int i2 = 0; i2 < 2; i2++) {
        int r0 = m0 + wm * 32 + i2 * 16 + group;
#pragma unroll
        for (int j = 0; j < 8; j++) {
            int cidx = n0 + wn * 64 + j * 8 + t4 * 2;
            float bv0 = bias[cidx], bv1 = bias[cidx + 1];
            float2 v0, v1;
            v0.x = acc[i2][j][0] + bv0; v0.y = acc[i2][j][1] + bv1;
            v1.x = acc[i2][j][2] + bv0; v1.y = acc[i2][j][3] + bv1;
            *(float2*)&C[(size_t)r0 * ldc + cidx]       = v0;
            *(float2*)&C[(size_t)(r0 + 8) * ldc + cidx] = v1;
        }
    }
}

// ---------------- NEW: unit-per-thread LSTM scan (H=128, NB=4) ------------
// 128 threads; thread j owns unit j: 4 gate rows x 4 batches.
// f32x2 lanes packed along k (even/odd partials) -> NO dup MOVs:
//   W in smem pre-packed as (k,k+1) float pairs; h stored batch-major so
//   (h[k],h[k+1]) is one 8-byte broadcast load. k rows [104,128) in regs.
// Ping-pong h buffer -> single __syncthreads per step. Gates stay in regs
// (no transpose phase). Writes split-bf16 A' [row][768] = [hi|hi|lo].
#define UKS2  52   // k-pairs in smem (k 0..103)
#define UKR2  12   // k-pairs in regs (k 104..127)
#define USMEM ((2 * UKS2 * 128 * 4 + 2 * 4 * 128) * 4)   // 217088 B

__global__ __launch_bounds__(128, 1)
void lstm_scan_u128(const float* __restrict__ xw,     // [T*B][1024]
                    const float* __restrict__ w_hh,   // [2][512][128]
                    __nv_bfloat16* __restrict__ ap)   // [T*B][768]
{
    const int j   = threadIdx.x;        // unit 0..127
    const int dir = blockIdx.y;
    const int b0  = blockIdx.x * 4;

    extern __shared__ float smf[];
    float* WtA = smf;                         // [UKS2][128][4]: g0,g1 k-pairs
    float* WtB = smf + UKS2 * 128 * 4;        // [UKS2][128][4]: g2,g3 k-pairs
    float* hp  = WtB + UKS2 * 128 * 4;        // [2][4][128] batch-major h

    const float* Wd = w_hh + (size_t)dir * 512 * 128;

    // cooperative W fill: coalesced LDG (k = j), scatter STS
#pragma unroll 4
    for (int r = 0; r < 512; r++) {
        float v = Wd[(size_t)r * 128 + j];
        int g = r >> 7, u = r & 127;
        int k2 = j >> 1, odd = j & 1;
        if (k2 < UKS2) {
            float* base = (g < 2) ? WtA : WtB;
            base[(k2 * 128 + u) * 4 + (g & 1) * 2 + odd] = v;
        }
    }

    // register-resident W for k in [104,128): (k,k+1) pairs per gate
    uint64_t wreg[4][UKR2];
#pragma unroll
    for (int g = 0; g < 4; g++) {
        const float* row = Wd + (size_t)(g * 128 + j) * 128 + 104;
#pragma unroll
        for (int k2 = 0; k2 < UKR2; k2++) {
            float2 w2 = *(const float2*)(row + 2 * k2);
            wreg[g][k2] = pack2(w2.x, w2.y);
        }
    }

    // zero h buffer 0
    for (int i = j; i < 512; i += 128) hp[i] = 0.0f;

    float c[4] = {0.f, 0.f, 0.f, 0.f};
    const int tstep = dir ? -1 : 1;
    int t = dir ? (T_SEQ - 1) : 0;
    const ptrdiff_t xstep = (ptrdiff_t)tstep * B_SZ * 1024;
    const float* xr = xw + ((size_t)t * B_SZ + b0) * 1024 + dir * 512 + j;

    float nx[4][4];
#pragma unroll
    for (int g = 0; g < 4; g++)
#pragma unroll
        for (int b = 0; b < 4; b++)
            nx[g][b] = xr[b * 1024 + g * 128];

    __syncthreads();

    for (int s = 0; s < T_SEQ; s++, t += tstep) {
        // acc lanes = (k-even partial, k-odd partial); seed xw in even lane
        uint64_t acc[4][4];
#pragma unroll
        for (int g = 0; g < 4; g++)
#pragma unroll
            for (int b = 0; b < 4; b++)
                acc[g][b] = pack2(nx[g][b], 0.0f);

        if (s + 1 < T_SEQ) {
            xr += xstep;
#pragma unroll
            for (int g = 0; g < 4; g++)
#pragma unroll
                for (int b = 0; b < 4; b++)
                    nx[g][b] = xr[b * 1024 + g * 128];
        }

        const float* hc = hp + (s & 1) * 512;       // read buffer

#pragma unroll 4
        for (int k2 = 0; k2 < UKS2; k2++) {
            const uint64_t* wpA = (const uint64_t*)(WtA + (k2 * 128 + j) * 4);
            const uint64_t* wpB = (const uint64_t*)(WtB + (k2 * 128 + j) * 4);
            uint64_t w0 = wpA[0], w1 = wpA[1];
            uint64_t w2 = wpB[0], w3 = wpB[1];
            uint64_t h0 = *(const uint64_t*)(hc + 0 * 128 + 2 * k2);
            uint64_t h1 = *(const uint64_t*)(hc + 1 * 128 + 2 * k2);
            uint64_t h2 = *(const uint64_t*)(hc + 2 * 128 + 2 * k2);
            uint64_t h3 = *(const uint64_t*)(hc + 3 * 128 + 2 * k2);
            fma2(acc[0][0], w0, h0); fma2(acc[0][1], w0, h1);
            fma2(acc[0][2], w0, h2); fma2(acc[0][3], w0, h3);
            fma2(acc[1][0], w1, h0); fma2(acc[1][1], w1, h1);
            fma2(acc[1][2], w1, h2); fma2(acc[1][3], w1, h3);
            fma2(acc[2][0], w2, h0); fma2(acc[2][1], w2, h1);
            fma2(acc[2][2], w2, h2); fma2(acc[2][3], w2, h3);
            fma2(acc[3][0], w3, h0); fma2(acc[3][1], w3, h1);
            fma2(acc[3][2], w3, h2); fma2(acc[3][3], w3, h3);
        }
#pragma unroll
        for (int k2 = 0; k2 < UKR2; k2++) {
            const float* hk = hc + 104 + 2 * k2;
            uint64_t h0 = *(const uint64_t*)(hk + 0 * 128);
            uint64_t h1 = *(const uint64_t*)(hk + 1 * 128);
            uint64_t h2 = *(const uint64_t*)(hk + 2 * 128);
            uint64_t h3 = *(const uint64_t*)(hk + 3 * 128);
#pragma unroll
            for (int g = 0; g < 4; g++) {
                fma2(acc[g][0], wreg[g][k2], h0);
                fma2(acc[g][1], wreg[g][k2], h1);
                fma2(acc[g][2], wreg[g][k2], h2);
                fma2(acc[g][3], wreg[g][k2], h3);
            }
        }

        float* hn = hp + ((s + 1) & 1) * 512;       // write buffer
        const int col = dir * 128 + j;
#pragma unroll
        for (int b = 0; b < 4; b++) {
            float xi = hadd2(acc[0][b]);
            float xf = hadd2(acc[1][b]);
            float xg = hadd2(acc[2][b]);
            float xo = hadd2(acc[3][b]);
            float si = sigf(xi), sf = sigf(xf), so = sigf(xo);
            float tg = tanhf_(xg);
            c[b] = fmaf(sf, c[b], si * tg);
            float h = so * tanhf_(c[b]);
            hn[b * 128 + j] = h;
            __nv_bfloat16 hi = __float2bfloat16(h);
            __nv_bfloat16 lo = __float2bfloat16(h - __bfloat162float(hi));
            size_t base = ((size_t)t * B_SZ + b0 + b) * 768;
            ap[base + col]       = hi;
            ap[base + 256 + col] = hi;
            ap[base + 512 + col] = lo;
        }
        __syncthreads();
    }
}

// ---------------- legacy LSTM scan (kept for layer 3, H=64) ----------------
template<int H, int NB, int KS, int NREG, int LDXW, int KOUT>
__global__ __launch_bounds__(4 * H, 1)
void lstm_scan(const float* __restrict__ xw, const float* __restrict__ w_hh,
               __nv_bfloat16* __restrict__ ap, float* __restrict__ h3out)
{
    constexpr int G4 = 4 * H;
    const int g   = threadIdx.x;
    const int dir = blockIdx.y;
    const int b0  = blockIdx.x * NB;

    extern __shared__ float smf[];
    float2* Wt2  = (float2*)smf;
    float*  hbuf = smf + KS * G4;
    float*  gates = hbuf + H * NB;

    const float* Wrow = w_hh + (size_t)dir * G4 * H + (size_t)g * H;
    for (int k2 = 0; k2 < KS / 2; k2++) {
        float2 w2;
        w2.x = Wrow[2 * k2];
        w2.y = Wrow[2 * k2 + 1];
        Wt2[k2 * G4 + g] = w2;
    }
    for (int i = g; i < H * NB; i += G4) hbuf[i] = 0.0f;
    float creg = 0.0f;
    __syncthreads();

    const uint32_t hb = smem_to_u32(hbuf);
    const int tstep = dir ? -1 : 1;
    int t = dir ? (T_SEQ - 1) : 0;
    const ptrdiff_t xstep = (ptrdiff_t)tstep * B_SZ * LDXW;
    const float* xr = xw + ((size_t)t * B_SZ + b0) * LDXW + dir * G4 + g;

    float nx[NB];
#pragma unroll
    for (int nb = 0; nb < NB; nb++) nx[nb] = xr[(size_t)nb * LDXW];

    for (int s = 0; s < T_SEQ; s++, t += tstep) {
        uint64_t acc01 = pack2(nx[0], nx[1]);

        if (s + 1 < T_SEQ) {
            xr += xstep;
#pragma unroll
            for (int nb = 0; nb < NB; nb++) nx[nb] = xr[(size_t)nb * LDXW];
        }

#pragma unroll 4
        for (int k2 = 0; k2 < KS / 2; k2++) {
            float2 w2 = Wt2[k2 * G4 + g];
            uint64_t ww0 = pack_dup(w2.x);
            uint64_t ww1 = pack_dup(w2.y);
            uint64_t ha, hbv;
            lds_v2u64(ha, hbv, hb + k2 * 16);
            fma2(acc01, ww0, ha);
            fma2(acc01, ww1, hbv);
        }

        float a0, a1;
        unpack2(acc01, a0, a1);
        gates[0 * G4 + g] = a0;
        gates[1 * G4 + g] = a1;
        __syncthreads();

        if (g < NB * H) {
            const int nb = g / H, jj = g - nb * H;
            const float* gr = gates + nb * G4;
            float xi = gr[jj];
            float xf = gr[H + jj];
            float xg = gr[2 * H + jj];
            float xo = gr[3 * H + jj];
            float si = sigf(xi), sf = sigf(xf), so = sigf(xo);
            float tg = tanhf_(xg);
            creg = fmaf(sf, creg, si * tg);
            float h = so * tanhf_(creg);
            hbuf[jj * NB + nb] = h;
            if constexpr (KOUT == 0) {
                if (s == T_SEQ - 1) h3out[(size_t)(b0 + nb) * 128 + jj] = h;
            }
        }
        __syncthreads();
    }
}

// ---------------- layer-3 backward: single step from zero state -----------
__global__ void lstm3_bwd_last(const float* __restrict__ xwb, float* __restrict__ h3)
{
    int b = blockIdx.x;
    int j = threadIdx.x;  // 0..63
    const float* gr = xwb + b * 256;
    float xi = gr[j], xg = gr[128 + j], xo = gr[192 + j];
    float c = sigf(xi) * tanhf_(xg);
    float h = sigf(xo) * tanhf_(c);
    h3[b * 128 + 64 + j] = h;
}

// ---------------- small FC ----------------
__global__ void fc_kernel(const float* __restrict__ in, const float* __restrict__ w,
                          const float* __restrict__ bias, float* __restrict__ out,
                          int K, int O, int do_relu)
{
    int b = blockIdx.x;
    extern __shared__ float s_in[];
    for (int k = threadIdx.x; k < K; k += blockDim.x) s_in[k] = in[(size_t)b * K + k];
    __syncthreads();
    for (int o = threadIdx.x; o < O; o += blockDim.x) {
        float acc = bias[o];
        const float* wr = w + (size_t)o * K;
        for (int k = 0; k < K; k++) acc = fmaf(s_in[k], wr[k], acc);
        if (do_relu) acc = fmaxf(acc, 0.0f);
        out[(size_t)b * O + o] = acc;
    }
}

// ---------------- host orchestration --------------------------------------
extern "C" void kernel_launch(void* const* d_in, const int* in_sizes, int n_in,
                              void* d_out, int out_size)
{
    const float* x      = (const float*)d_in[0];
    const float* conv_w = (const float*)d_in[1];
    const float* conv_b = (const float*)d_in[2];
    const float* w_ih1  = (const float*)d_in[3];
    const float* w_hh1  = (const float*)d_in[4];
    const float* b1     = (const float*)d_in[5];
    const float* w_ih2  = (const float*)d_in[6];
    const float* w_hh2  = (const float*)d_in[7];
    const float* b2     = (const float*)d_in[8];
    const float* w_ih3  = (const float*)d_in[9];
    const float* w_hh3  = (const float*)d_in[10];
    const float* b3     = (const float*)d_in[11];
    const float* fc1_w  = (const float*)d_in[12];
    const float* fc1_b  = (const float*)d_in[13];
    const float* fc2_w  = (const float*)d_in[14];
    const float* fc2_b  = (const float*)d_in[15];
    const float* fc3_w  = (const float*)d_in[16];
    const float* fc3_b  = (const float*)d_in[17];
    const float* fc4_w  = (const float*)d_in[18];
    const float* fc4_b  = (const float*)d_in[19];
    float* out = (float*)d_out;

    float *pXW, *pXWB3, *pH3, *pF1, *pF2, *pF3;
    __nv_bfloat16 *pAp, *pWp;
    cudaGetSymbolAddress((void**)&pXW,   g_XW);
    cudaGetSymbolAddress((void**)&pAp,   g_Ap);
    cudaGetSymbolAddress((void**)&pWp,   g_Wp);
    cudaGetSymbolAddress((void**)&pXWB3, g_XWB3);
    cudaGetSymbolAddress((void**)&pH3,   g_H3);
    cudaGetSymbolAddress((void**)&pF1,   g_F1);
    cudaGetSymbolAddress((void**)&pF2,   g_F2);
    cudaGetSymbolAddress((void**)&pF3,   g_F3);

    const int M = T_SEQ * B_SZ;  // 262144

    constexpr int SMEM64 = (64 * 256 + 64 * 2 + 2 * 256) * 4;   // legacy L3
    cudaFuncSetAttribute(lstm_scan_u128,
                         cudaFuncAttributeMaxDynamicSharedMemorySize, USMEM);
    cudaFuncSetAttribute(lstm_scan<64, 2, 64, 0, 256, 0>,
                         cudaFuncAttributeMaxDynamicSharedMemorySize, SMEM64);
    cudaFuncSetAttribute(gemm_mma,
                         cudaFuncAttributeMaxDynamicSharedMemorySize, GSMEM);

    // 1) conv -> A' [t*B+b][192] (fused bf16 split)
    conv_kernel<<<dim3(T_SEQ / 4, B_SZ), 256>>>(x, conv_w, conv_b, pAp);

    // 2) layer 1: W split (K=64 -> 192) + GEMM + unit-scan (writes A'[768])
    split2_kernel<<<(1024 * 32 + 255) / 256, 256>>>(w_ih1, pWp, 1024 * 32, 32, 64);
    gemm_mma<<<dim3(8, M / 128), 256, GSMEM>>>(pAp, pWp, b1, pXW, 192, 1024);
    lstm_scan_u128<<<dim3(B_SZ / 4, 2), 128, USMEM>>>(pXW, w_hh1, pAp);

    // 3) layer 2: K=256 -> 768
    split2_kernel<<<(1024 * 128 + 255) / 256, 256>>>(w_ih2, pWp, 1024 * 128, 128, 256);
    gemm_mma<<<dim3(8, M / 128), 256, GSMEM>>>(pAp, pWp, b2, pXW, 768, 1024);
    lstm_scan_u128<<<dim3(B_SZ / 4, 2), 128, USMEM>>>(pXW, w_hh2, pAp);

    // 4) layer 3 forward: N=256 (fwd gates only), full scan, keep last h
    split2_kernel<<<(512 * 128 + 255) / 256, 256>>>(w_ih3, pWp, 512 * 128, 128, 256);
    gemm_mma<<<dim3(2, M / 128), 256, GSMEM>>>(pAp, pWp, b3, pXW, 768, 256);
    lstm_scan<64, 2, 64, 0, 256, 0>
        <<<dim3(B_SZ / 2, 1), 256, SMEM64>>>(pXW, w_hh3, nullptr, pH3);

    // 5) layer 3 backward at t=T-1 only: one step from zero state
    gemm_mma<<<dim3(2, 2), 256, GSMEM>>>(
        pAp + (size_t)(T_SEQ - 1) * B_SZ * 768,
        pWp + (size_t)256 * 768, b3 + 256, pXWB3, 768, 256);
    lstm3_bwd_last<<<B_SZ, 64>>>(pXWB3, pH3);

    // 6) FC head
    fc_kernel<<<B_SZ, 128, 128 * 4>>>(pH3, fc1_w, fc1_b, pF1, 128, 512, 1);
    fc_kernel<<<B_SZ, 128, 512 * 4>>>(pF1, fc2_w, fc2_b, pF2, 512, 256, 1);
    fc_kernel<<<B_SZ, 128, 256 * 4>>>(pF2, fc3_w, fc3_b, pF3, 256, 128, 1);
    fc_kernel<<<B_SZ, 64, 128 * 4>>>(pF3, fc4_w, fc4_b, out, 128, 2, 0);

    (void)in_sizes; (void)n_in; (void)out_size;
}